// round 1
// baseline (speedup 1.0000x reference)
#include <cuda_runtime.h>
#include <math.h>

#define Bn 64
#define Tn 256
#define In 512
#define Hn 800
#define FH 3200   // 4*H

// Scratch: proj[dir][(b*T + t)*4H + g*H + h]
__device__ float g_proj[2][Bn * Tn * FH];
// Recurrent state: h double-buffered per direction, c single
__device__ float g_h[2][2][Bn * Hn];
__device__ float g_c[2][Bn * Hn];

__global__ void init_state() {
    int i = blockIdx.x * blockDim.x + threadIdx.x;
    if (i < Bn * Hn) {
        g_h[0][0][i] = 0.f; g_h[0][1][i] = 0.f;
        g_h[1][0][i] = 0.f; g_h[1][1][i] = 0.f;
        g_c[0][i] = 0.f;    g_c[1][i] = 0.f;
    }
}

// ---------------------------------------------------------------------------
// proj[dir][(b*T+t)*4H + g*H + n] = sum_i x[b,t,i]*mask[b,g,i]*W[i, g*H+n] + bias[g*H+n]
// GEMM: M = B*T = 16384, N = H = 800 (per gate), K = I = 512
// Tile: BM=64, BN=80 (800 = 10*80, no bounds checks), BK=16.
// 128 threads, each computes 8x5 outputs.
// grid = (10 n-tiles, 256 m-tiles, 8 = dir*4+g)
// ---------------------------------------------------------------------------
__global__ void proj_kernel(const float* __restrict__ x,
                            const float* __restrict__ mask_f,
                            const float* __restrict__ mask_b,
                            const float* __restrict__ W_f,
                            const float* __restrict__ W_b,
                            const float* __restrict__ bias_f,
                            const float* __restrict__ bias_b)
{
    constexpr int BM = 64, BN = 80, BK = 16;
    const int z   = blockIdx.z;
    const int dir = z >> 2;
    const int g   = z & 3;
    const int m0  = blockIdx.y * BM;
    const int n0  = blockIdx.x * BN;
    const float* __restrict__ W    = dir ? W_b    : W_f;
    const float* __restrict__ mask = dir ? mask_b : mask_f;
    const float* __restrict__ bias = dir ? bias_b : bias_f;

    __shared__ float As[BK][BM];
    __shared__ float Bs[BK][BN];

    const int tid = threadIdx.x;   // 128
    const int mt  = tid & 7;       // 8 row groups (TM=8, rows mt + r*8)
    const int nt  = tid >> 3;      // 16 col groups (TN=5, cols nt*5 + c)

    float acc[8][5];
#pragma unroll
    for (int r = 0; r < 8; r++)
#pragma unroll
        for (int c = 0; c < 5; c++) acc[r][c] = 0.f;

    for (int k0 = 0; k0 < In; k0 += BK) {
        // A tile: 64 rows x 16 k = 256 float4, 2 per thread, mask applied
#pragma unroll
        for (int r = 0; r < 2; r++) {
            int idx = tid + r * 128;
            int k4  = idx & 3;
            int m   = idx >> 2;          // 0..63
            int bt  = m0 + m;
            int b   = bt >> 8;           // bt / T
            const float4 xv = *(const float4*)(x    + (size_t)bt * In + k0 + k4 * 4);
            const float4 mv = *(const float4*)(mask + (size_t)b * (4 * In) + (size_t)g * In + k0 + k4 * 4);
            As[k4 * 4 + 0][m] = xv.x * mv.x;
            As[k4 * 4 + 1][m] = xv.y * mv.y;
            As[k4 * 4 + 2][m] = xv.z * mv.z;
            As[k4 * 4 + 3][m] = xv.w * mv.w;
        }
        // B tile: 16 x 80 = 1280 elems, 10 per thread
#pragma unroll
        for (int r = 0; r < 10; r++) {
            int idx = tid + r * 128;
            int n   = idx % 80;
            int k   = idx / 80;
            Bs[k][n] = W[(size_t)(k0 + k) * FH + (size_t)g * Hn + n0 + n];
        }
        __syncthreads();
#pragma unroll
        for (int k = 0; k < BK; k++) {
            float af[8], bf[5];
#pragma unroll
            for (int r = 0; r < 8; r++) af[r] = As[k][mt + r * 8];
#pragma unroll
            for (int c = 0; c < 5; c++) bf[c] = Bs[k][nt * 5 + c];
#pragma unroll
            for (int r = 0; r < 8; r++)
#pragma unroll
                for (int c = 0; c < 5; c++)
                    acc[r][c] = fmaf(af[r], bf[c], acc[r][c]);
        }
        __syncthreads();
    }

    float* __restrict__ outp = g_proj[dir];
#pragma unroll
    for (int r = 0; r < 8; r++) {
        int bt = m0 + mt + r * 8;
#pragma unroll
        for (int c = 0; c < 5; c++) {
            int n = n0 + nt * 5 + c;
            outp[(size_t)bt * FH + (size_t)g * Hn + n] = acc[r][c] + bias[g * Hn + n];
        }
    }
}

// ---------------------------------------------------------------------------
// One timestep, both directions (blockIdx.y = dir).
// z(64, 4H) = h_prev(64,800) @ U(800, 4H);  each block owns 8 h-columns x 4 gates
// so the gate nonlinearity + c/h update is thread-local.
// Tile: BM=64 (all batch), 8 h-cols * 4 gates = 32 N cols, BK=16, K=800.
// 128 threads: jt = tid&7 (h col), mt = tid>>3 (batch group, TM=4: b = mt + r*16).
// grid = (100, 2)
// ---------------------------------------------------------------------------
__global__ void step_kernel(const float* __restrict__ U_f,
                            const float* __restrict__ U_b,
                            float* __restrict__ out,
                            int t)
{
    constexpr int BK = 16;
    const int dir = blockIdx.y;
    const int n0  = blockIdx.x * 8;
    const float* __restrict__ U = dir ? U_b : U_f;
    const int cur = t & 1;
    const int nxt = 1 - cur;
    const float* __restrict__ hprev = g_h[dir][cur];
    const int t_eff = dir ? (Tn - 1 - t) : t;    // proj time index (backward reads reversed)

    __shared__ float As[BK][64];
    __shared__ float Bs[BK][32];

    const int tid = threadIdx.x;  // 128
    const int jt  = tid & 7;      // h column within tile
    const int mt  = tid >> 3;     // 0..15 batch group

    float acc[4][4];              // [batch r][gate]
#pragma unroll
    for (int r = 0; r < 4; r++)
#pragma unroll
        for (int g = 0; g < 4; g++) acc[r][g] = 0.f;

    for (int k0 = 0; k0 < Hn; k0 += BK) {
        // A: h_prev tile 64x16 = 256 float4, 2 per thread
#pragma unroll
        for (int r = 0; r < 2; r++) {
            int idx = tid + r * 128;
            int k4  = idx & 3;
            int m   = idx >> 2;
            const float4 hv = *(const float4*)(hprev + (size_t)m * Hn + k0 + k4 * 4);
            As[k4 * 4 + 0][m] = hv.x;
            As[k4 * 4 + 1][m] = hv.y;
            As[k4 * 4 + 2][m] = hv.z;
            As[k4 * 4 + 3][m] = hv.w;
        }
        // B: U tile 16 x (4 gates x 8 cols) = 512 elems, 4 per thread
#pragma unroll
        for (int r = 0; r < 4; r++) {
            int idx = tid + r * 128;
            int col = idx & 31;          // g*8 + j
            int k   = idx >> 5;
            int gg  = col >> 3;
            int j   = col & 7;
            Bs[k][col] = U[(size_t)(k0 + k) * FH + (size_t)gg * Hn + n0 + j];
        }
        __syncthreads();
#pragma unroll
        for (int k = 0; k < BK; k++) {
            float af[4], bf[4];
#pragma unroll
            for (int r = 0; r < 4; r++) af[r] = As[k][mt + r * 16];
#pragma unroll
            for (int g = 0; g < 4; g++) bf[g] = Bs[k][g * 8 + jt];
#pragma unroll
            for (int r = 0; r < 4; r++)
#pragma unroll
                for (int g = 0; g < 4; g++)
                    acc[r][g] = fmaf(af[r], bf[g], acc[r][g]);
        }
        __syncthreads();
    }

    // Gate math + state update + output write
    const int hh = n0 + jt;
    const float* __restrict__ proj = g_proj[dir];
#pragma unroll
    for (int r = 0; r < 4; r++) {
        int b = mt + r * 16;
        size_t pbase = ((size_t)b * Tn + t_eff) * FH;
        float zi = acc[r][0] + proj[pbase + 0 * Hn + hh];
        float zf = acc[r][1] + proj[pbase + 1 * Hn + hh];
        float zg = acc[r][2] + proj[pbase + 2 * Hn + hh];
        float zo = acc[r][3] + proj[pbase + 3 * Hn + hh];

        float ig = 1.f / (1.f + expf(-zi));
        float fg = 1.f / (1.f + expf(-zf));
        float gg = tanhf(zg);
        float og = 1.f / (1.f + expf(-zo));

        size_t ci = (size_t)b * Hn + hh;
        float cv = fg * g_c[dir][ci] + ig * gg;
        float hv = og * tanhf(cv);
        g_c[dir][ci] = cv;
        g_h[dir][nxt][ci] = hv;

        // Hcat[b, t, dir*H + hh]  (backward outputs are in processing order)
        out[((size_t)b * Tn + t) * (2 * Hn) + (size_t)dir * Hn + hh] = hv;
        if (t == Tn - 1) {
            size_t hcat0 = (size_t)Bn * Tn * (2 * Hn);
            size_t ccat0 = hcat0 + (size_t)Bn * (2 * Hn);
            out[hcat0 + (size_t)b * (2 * Hn) + (size_t)dir * Hn + hh] = hv;
            out[ccat0 + (size_t)b * (2 * Hn) + (size_t)dir * Hn + hh] = cv;
        }
    }
}

extern "C" void kernel_launch(void* const* d_in, const int* in_sizes, int n_in,
                              void* d_out, int out_size)
{
    const float* x      = (const float*)d_in[0];
    const float* mask_f = (const float*)d_in[1];
    const float* mask_b = (const float*)d_in[2];
    const float* W_f    = (const float*)d_in[3];
    const float* U_f    = (const float*)d_in[4];
    const float* b_f    = (const float*)d_in[5];
    const float* W_b    = (const float*)d_in[6];
    const float* U_b    = (const float*)d_in[7];
    const float* b_b    = (const float*)d_in[8];
    float* out = (float*)d_out;

    init_state<<<(Bn * Hn + 255) / 256, 256>>>();
    proj_kernel<<<dim3(10, 256, 8), 128>>>(x, mask_f, mask_b, W_f, W_b, b_f, b_b);
    for (int t = 0; t < Tn; t++)
        step_kernel<<<dim3(100, 2), 128>>>(U_f, U_b, out, t);
}